// round 7
// baseline (speedup 1.0000x reference)
#include <cuda_runtime.h>
#include <cstdint>

// ViT patch embedding, mma.sync tf32. M=25088, N=768, K=768 fused with
// patchify + bias + cls. Block tile 128x256, BK=32, warp grid 2(m)x4(n),
// warp tile 64x64 (acc=128 regs), 256 threads, 1 block/SM (full RF for
// software pipelining). 3-stage cp.async ring, 32B-rotation swizzle
// (conflict-free STS16 + LDS.64 frag reads, k-pair slot permutation).

#define NPATCH  196
#define NIMG    128
#define KDIM    768
#define NDIM    768
#define MTOT    25088

#define BM 128
#define BN 256
#define BK 32
#define NITER (KDIM / BK)            // 24
#define ASTAGE_B 16384               // 128 rows x 128B
#define BSTAGE_B 32768               // 256 rows x 128B
#define STAGE_BYTES (ASTAGE_B + BSTAGE_B)   // 48KB
#define NSTG 3
#define SMEM_BYTES (NSTG * STAGE_BYTES)     // 147456

__device__ float W_pre[NDIM * KDIM];

__device__ __forceinline__ void mma_tf32(float* c, const uint32_t* a, const uint32_t* b) {
    asm volatile(
        "mma.sync.aligned.m16n8k8.row.col.f32.tf32.tf32.f32 "
        "{%0,%1,%2,%3}, {%4,%5,%6,%7}, {%8,%9}, {%0,%1,%2,%3};\n"
        : "+f"(c[0]), "+f"(c[1]), "+f"(c[2]), "+f"(c[3])
        : "r"(a[0]), "r"(a[1]), "r"(a[2]), "r"(a[3]), "r"(b[0]), "r"(b[1]));
}
__device__ __forceinline__ void cp16(uint32_t s, const void* g) {
    asm volatile("cp.async.cg.shared.global [%0], [%1], 16;\n" :: "r"(s), "l"(g));
}
__device__ __forceinline__ void cp_commit() { asm volatile("cp.async.commit_group;\n"); }
template <int N>
__device__ __forceinline__ void cp_wait() { asm volatile("cp.async.wait_group %0;\n" :: "n"(N)); }

__global__ void round_w(const float* __restrict__ W) {
    int i = blockIdx.x * 256 + threadIdx.x;
    if (i < NDIM * KDIM) {
        uint32_t r;
        asm("cvt.rna.tf32.f32 %0, %1;" : "=r"(r) : "f"(W[i]));
        W_pre[i] = __uint_as_float(r);
    }
}

__global__ __launch_bounds__(256, 1) void vit_gemm(
    const float* __restrict__ images,
    const float* __restrict__ bias,
    const float* __restrict__ cls,
    float* __restrict__ out)
{
    extern __shared__ __align__(16) char smc[];

    const int tid  = threadIdx.x;
    const int lane = tid & 31;
    const int warp = tid >> 5;          // 0..7
    const int wm   = warp & 1;          // 2 m-positions of 64
    const int wn   = warp >> 1;         // 4 n-positions of 64
    const int g    = lane >> 2;         // 0..7
    const int tg   = lane & 3;          // 0..3

    const int bm = blockIdx.y * BM;
    const int bn = blockIdx.x * BN;

    // ---------------- loader mapping (quarter-warp = one 128B row) ----------------
    const int lq = lane >> 3;           // 0..3
    const int lc = lane & 7;            // chunk 0..7
    const uint32_t swoff = (uint32_t)((16 * lc + 32 * lq) & 127);

    // A: rows 16*warp + 4i + lq (i=0..3); pixel sub-row (lc>>2), col (lc&3)*4
    const float* asrc[4];
    #pragma unroll
    for (int i = 0; i < 4; ++i) {
        const int r   = 16 * warp + 4 * i + lq;
        const int m   = bm + r;
        const int img = m / NPATCH;
        const int pch = m - img * NPATCH;
        const int Pi  = pch / 14;
        const int Pj  = pch - Pi * 14;
        asrc[i] = images + (size_t)img * 150528 + (size_t)(Pi * 16 + (lc >> 2)) * 224
                         + Pj * 16 + (lc & 3) * 4;
    }
    const uint32_t sts_a0 = (uint32_t)(16 * warp + lq) * 128u + swoff;

    // B: rows 32*warp + 4i + lq (i=0..7): single base + i*3072 floats
    const float* bsrc0 = W_pre + (size_t)(bn + 32 * warp + lq) * KDIM + 4 * lc;
    const uint32_t sts_b0 = (uint32_t)(32 * warp + lq) * 128u + swoff;

    const uint32_t sbase = (uint32_t)__cvta_generic_to_shared(smc);

    auto load_tile = [&](int it) {
        const int st  = it - (it / NSTG) * NSTG;
        const int k0  = it * BK;
        const int cch = k0 >> 8;
        const int ph0 = (k0 >> 4) & 15;
        const size_t aoff = (size_t)cch * 50176 + (size_t)ph0 * 224;
        const uint32_t sa = sbase + (uint32_t)st * STAGE_BYTES;
        const uint32_t sb = sa + ASTAGE_B;
        #pragma unroll
        for (int i = 0; i < 4; ++i)
            cp16(sa + sts_a0 + i * 512u, asrc[i] + aoff);
        #pragma unroll
        for (int i = 0; i < 8; ++i)
            cp16(sb + sts_b0 + i * 512u, bsrc0 + i * 3072 + k0);
    };

    float acc[4][8][4];
    #pragma unroll
    for (int mt = 0; mt < 4; ++mt)
        #pragma unroll
        for (int nt = 0; nt < 8; ++nt)
            #pragma unroll
            for (int r = 0; r < 4; ++r) acc[mt][nt][r] = 0.f;

    load_tile(0); cp_commit();
    load_tile(1); cp_commit();

    const uint32_t fr_rot = (uint32_t)(32 * (g & 3));

    for (int it = 0; it < NITER; ++it) {
        if (it == NITER - 1) cp_wait<0>(); else cp_wait<1>();
        __syncthreads();

        const int st = it - (it / NSTG) * NSTG;
        const char* Ab = smc + st * STAGE_BYTES;
        const char* Bb = Ab + ASTAGE_B;

        #pragma unroll
        for (int ks = 0; ks < 4; ++ks) {
            const uint32_t swz = (uint32_t)((32 * ks + 8 * tg + fr_rot) & 127);
            uint32_t af[4][4], bf[8][2];
            #pragma unroll
            for (int mt = 0; mt < 4; ++mt) {
                const int row = wm * 64 + mt * 16 + g;
                const float2 v0 = *reinterpret_cast<const float2*>(Ab + row * 128 + swz);
                const float2 v1 = *reinterpret_cast<const float2*>(Ab + (row + 8) * 128 + swz);
                af[mt][0] = __float_as_uint(v0.x);   // k = 2tg   (slot tg)
                af[mt][2] = __float_as_uint(v0.y);   // k = 2tg+1 (slot tg+4)
                af[mt][1] = __float_as_uint(v1.x);
                af[mt][3] = __float_as_uint(v1.y);
            }
            #pragma unroll
            for (int nt = 0; nt < 8; ++nt) {
                const int col = wn * 64 + nt * 8 + g;
                const float2 v = *reinterpret_cast<const float2*>(Bb + col * 128 + swz);
                bf[nt][0] = __float_as_uint(v.x);
                bf[nt][1] = __float_as_uint(v.y);
            }
            #pragma unroll
            for (int mt = 0; mt < 4; ++mt)
                #pragma unroll
                for (int nt = 0; nt < 8; ++nt)
                    mma_tf32(acc[mt][nt], af[mt], bf[nt]);

            if (ks == 0 && it + 2 < NITER) { load_tile(it + 2); cp_commit(); }
        }
    }

    // ---------------- epilogue: bias + scatter ----------------
    float bv[8][2];
    #pragma unroll
    for (int nt = 0; nt < 8; ++nt) {
        const int col = bn + wn * 64 + nt * 8 + tg * 2;
        bv[nt][0] = bias[col];
        bv[nt][1] = bias[col + 1];
    }

    #pragma unroll
    for (int mt = 0; mt < 4; ++mt) {
        #pragma unroll
        for (int rh = 0; rh < 2; ++rh) {
            const int m     = bm + wm * 64 + mt * 16 + rh * 8 + g;
            const int img   = m / NPATCH;
            const int patch = m - img * NPATCH;
            float* orow = out + ((size_t)img * 197 + patch + 1) * NDIM;
            #pragma unroll
            for (int nt = 0; nt < 8; ++nt) {
                const int col = bn + wn * 64 + nt * 8 + tg * 2;
                float2 v;
                v.x = acc[mt][nt][rh * 2 + 0] + bv[nt][0];
                v.y = acc[mt][nt][rh * 2 + 1] + bv[nt][1];
                *reinterpret_cast<float2*>(orow + col) = v;
            }
        }
    }

    // ---------------- fused CLS rows ----------------
    if (blockIdx.y == 0) {
        const int gid = blockIdx.x * 256 + tid;            // 0..767
        const float4* c4 = (const float4*)cls;
        for (int i = gid; i < NIMG * (NDIM / 4); i += 768) {
            const int img = i / (NDIM / 4);
            const int n4  = i - img * (NDIM / 4);
            reinterpret_cast<float4*>(out + (size_t)img * 197 * NDIM)[n4] = c4[n4];
        }
    }
}

extern "C" void kernel_launch(void* const* d_in, const int* in_sizes, int n_in,
                              void* d_out, int out_size) {
    const float* images = (const float*)d_in[0];
    const float* W      = (const float*)d_in[1];
    const float* b      = (const float*)d_in[2];
    const float* cls    = (const float*)d_in[3];
    float* out          = (float*)d_out;

    cudaFuncSetAttribute(vit_gemm, cudaFuncAttributeMaxDynamicSharedMemorySize, SMEM_BYTES);

    round_w<<<(NDIM * KDIM + 255) / 256, 256>>>(W);
    dim3 grid(NDIM / BN, MTOT / BM);   // (3, 196), n fastest for A L2 reuse
    vit_gemm<<<grid, 256, SMEM_BYTES>>>(images, b, cls, out);
}